// round 4
// baseline (speedup 1.0000x reference)
#include <cuda_runtime.h>
#include <cuda_bf16.h>
#include <cstdint>
#include <math.h>

// ---------------------------------------------------------------------------
// Problem constants
// ---------------------------------------------------------------------------
constexpr int B = 4;
constexpr int S = 2048;
constexpr int E = 1024;
constexpr int M_ROWS = B * S;   // 8192

// GEMM tiling: CTA 128x256, KB=64 bf16 per chunk (128B swizzled rows)
constexpr int TM = 128, TN = 256, KB = 64;
constexpr int A_TILE_BYTES = 128 * 128;        // 16KB
constexpr int B_TILE_BYTES = 256 * 128;        // 32KB
constexpr int STAGE_BYTES = 2 * A_TILE_BYTES + 2 * B_TILE_BYTES;  // 96KB
constexpr int NSTAGE = 2;
constexpr int SMEM_SZ = NSTAGE * STAGE_BYTES;  // 192KB
constexpr int EPIT = 260;                      // fp32 epilogue pitch (words)

// ---------------------------------------------------------------------------
// Scratch (device globals — no allocations allowed)
// ---------------------------------------------------------------------------
__device__ __nv_bfloat16 g_qh[(size_t)M_ROWS * E], g_ql[(size_t)M_ROWS * E];
__device__ __nv_bfloat16 g_kh[(size_t)M_ROWS * E], g_kl[(size_t)M_ROWS * E];
__device__ __nv_bfloat16 g_vh[(size_t)M_ROWS * E], g_vl[(size_t)M_ROWS * E];
__device__ __nv_bfloat16 g_wqh[(size_t)E * E], g_wql[(size_t)E * E];
__device__ __nv_bfloat16 g_wkh[(size_t)E * E], g_wkl[(size_t)E * E];
__device__ __nv_bfloat16 g_wvh[(size_t)E * E], g_wvl[(size_t)E * E];
__device__ __nv_bfloat16 g_woh[(size_t)E * E], g_wol[(size_t)E * E];
__device__ __nv_bfloat16 g_Qh[(size_t)M_ROWS * E], g_Ql[(size_t)M_ROWS * E];
__device__ __nv_bfloat16 g_Kh[(size_t)M_ROWS * E], g_Kl[(size_t)M_ROWS * E];
__device__ __nv_bfloat16 g_Vth[(size_t)B * E * S], g_Vtl[(size_t)B * E * S];
__device__ float         g_Sc[(size_t)B * S * S];
__device__ __nv_bfloat16 g_Ph[(size_t)B * S * S], g_Pl[(size_t)B * S * S];
__device__ __nv_bfloat16 g_AOh[(size_t)M_ROWS * E], g_AOl[(size_t)M_ROWS * E];

// ---------------------------------------------------------------------------
// PTX helpers (Ampere-compatible only: cp.async, ldmatrix, mma.sync)
// ---------------------------------------------------------------------------
__device__ __forceinline__ uint32_t smem_u32(const void* p) {
    uint32_t a;
    asm("{ .reg .u64 t; cvta.to.shared.u64 t, %1; cvt.u32.u64 %0, t; }" : "=r"(a) : "l"(p));
    return a;
}
#define SWZ(o) ((uint32_t)(o) ^ ((((uint32_t)(o)) >> 3) & 0x70))

#define CP_ASYNC16(dst, src) \
    asm volatile("cp.async.cg.shared.global [%0], [%1], 16;" :: "r"(dst), "l"(src) : "memory")
#define CP_COMMIT() asm volatile("cp.async.commit_group;" ::: "memory")
#define CP_WAIT0()  asm volatile("cp.async.wait_group 0;" ::: "memory")
#define CP_WAIT1()  asm volatile("cp.async.wait_group 1;" ::: "memory")

#define LDSM4(r0, r1, r2, r3, a) \
    asm volatile("ldmatrix.sync.aligned.m8n8.x4.shared.b16 {%0,%1,%2,%3}, [%4];" \
                 : "=r"(r0), "=r"(r1), "=r"(r2), "=r"(r3) : "r"(a))

#define MMA16816(c, a, b0, b1) \
    asm volatile("mma.sync.aligned.m16n8k16.row.col.f32.bf16.bf16.f32 " \
                 "{%0,%1,%2,%3},{%4,%5,%6,%7},{%8,%9},{%0,%1,%2,%3};" \
                 : "+f"((c)[0]), "+f"((c)[1]), "+f"((c)[2]), "+f"((c)[3]) \
                 : "r"((a)[0]), "r"((a)[1]), "r"((a)[2]), "r"((a)[3]), \
                   "r"(b0), "r"(b1))

// ---------------------------------------------------------------------------
// fp32 -> (bf16 hi, bf16 lo) elementwise conversion
// ---------------------------------------------------------------------------
__global__ __launch_bounds__(256) void cvt_pair(const float* __restrict__ in,
                                                __nv_bfloat16* __restrict__ h,
                                                __nv_bfloat16* __restrict__ l, int n)
{
    int i = (blockIdx.x * 256 + threadIdx.x) * 8;
    if (i >= n) return;
    float4 a = *(const float4*)(in + i);
    float4 b2 = *(const float4*)(in + i + 4);
    float v[8] = {a.x, a.y, a.z, a.w, b2.x, b2.y, b2.z, b2.w};
    unsigned short hb[8], lb[8];
    #pragma unroll
    for (int j = 0; j < 8; j++) {
        __nv_bfloat16 hv = __float2bfloat16(v[j]);
        float lo = v[j] - __bfloat162float(hv);
        __nv_bfloat16 lv = __float2bfloat16(lo);
        hb[j] = *(unsigned short*)&hv;
        lb[j] = *(unsigned short*)&lv;
    }
    *(uint4*)(h + i) = *(uint4*)hb;
    *(uint4*)(l + i) = *(uint4*)lb;
}

// ---------------------------------------------------------------------------
// Fused causal softmax: fp32 scores -> bf16-pair probabilities (zeros padded
// to the 128-multiple so attn@V can run dense up to the diagonal tile).
// ---------------------------------------------------------------------------
__global__ __launch_bounds__(256) void softmax_pair(const float* __restrict__ Sc,
                                                    __nv_bfloat16* __restrict__ Ph,
                                                    __nv_bfloat16* __restrict__ Pl)
{
    const int row = blockIdx.x;
    const int b = row >> 11, q = row & (S - 1);
    const float* ptr = Sc + (size_t)b * S * S + (size_t)q * S;
    const int len = q + 1;
    const int plen = ((q >> 7) + 1) << 7;
    const int tid = threadIdx.x;

    float vals[8];
    float m = -INFINITY;
    #pragma unroll
    for (int i = 0; i < 8; i++) {
        int k = tid + i * 256;
        vals[i] = (k < len) ? ptr[k] : -INFINITY;
        m = fmaxf(m, vals[i]);
    }
    __shared__ float red[256];
    red[tid] = m;
    __syncthreads();
    for (int s = 128; s > 0; s >>= 1) {
        if (tid < s) red[tid] = fmaxf(red[tid], red[tid + s]);
        __syncthreads();
    }
    m = red[0];
    __syncthreads();
    float sum = 0.f;
    #pragma unroll
    for (int i = 0; i < 8; i++) {
        int k = tid + i * 256;
        vals[i] = (k < len) ? __expf(vals[i] - m) : 0.f;
        sum += vals[i];
    }
    red[tid] = sum;
    __syncthreads();
    for (int s = 128; s > 0; s >>= 1) {
        if (tid < s) red[tid] += red[tid + s];
        __syncthreads();
    }
    const float inv = 1.0f / red[0];

    __nv_bfloat16* ph = Ph + (size_t)b * S * S + (size_t)q * S;
    __nv_bfloat16* pl = Pl + (size_t)b * S * S + (size_t)q * S;
    #pragma unroll
    for (int i = 0; i < 8; i++) {
        int k = tid + i * 256;
        if (k < plen) {
            float p = vals[i] * inv;
            __nv_bfloat16 h = __float2bfloat16(p);
            ph[k] = h;
            pl[k] = __float2bfloat16(p - __bfloat162float(h));
        }
    }
}

// ---------------------------------------------------------------------------
// HMMA GEMM, NT: C[M,N] = A[M,K] * Bop[N,K]^T, split-bf16 (3 MMA terms).
//   MODE 0: fp32 out + bias      MODE 1: bf16-pair out + bias, * scale
//   MODE 2: fp32 out (plain)     MODE 3: bf16-pair out (no bias)
//   MODE 4: bf16-pair TRANSPOSED out (V -> Vt[b][e][s])
//   CAUSAL: skip tiles above diagonal.  ATTNV: clip K at m0+128.
// CTA tile 128x256, 8 warps of 64x64, 2-stage cp.async double buffer.
// ---------------------------------------------------------------------------
template<int MODE, bool CAUSAL, bool ATTNV>
__global__ __launch_bounds__(256, 1) void gemm_mma(
    const __nv_bfloat16* __restrict__ Ah, const __nv_bfloat16* __restrict__ Al,
    const __nv_bfloat16* __restrict__ Bh, const __nv_bfloat16* __restrict__ Bl,
    const float* __restrict__ bias, float scale,
    float* __restrict__ outF, __nv_bfloat16* __restrict__ outH, __nv_bfloat16* __restrict__ outL,
    int K, int lda, int ldb, int ldc,
    size_t sA, size_t sB, size_t sC)
{
    const int m0 = blockIdx.y * TM, n0 = blockIdx.x * TN, b = blockIdx.z;
    if (CAUSAL && n0 > m0) return;

    Ah += (size_t)b * sA; Al += (size_t)b * sA;
    Bh += (size_t)b * sB; Bl += (size_t)b * sB;

    extern __shared__ __align__(1024) char smem[];
    const uint32_t smb = smem_u32(smem);
    const int tid = threadIdx.x;
    const int wid = tid >> 5, lane = tid & 31;
    const int warp_m = wid >> 2;        // 0..1 -> 64-row half
    const int warp_n = wid & 3;         // 0..3 -> 64-col quarter
    const int NC = ATTNV ? (m0 + TM) / KB : K / KB;

    // stage layout: [Ah 16K][Al 16K][Bh 32K][Bl 32K]
    auto load_chunk = [&](int c, int s) {
        const int k0 = c * KB;
        const uint32_t stage = smb + s * STAGE_BYTES;
        // A tiles: 128 rows x 8 x 16B lines -> 4 iters per tile
        #pragma unroll
        for (int t = 0; t < 2; t++) {
            const __nv_bfloat16* g = t ? Al : Ah;
            const uint32_t tb = stage + t * A_TILE_BYTES;
            #pragma unroll
            for (int i = 0; i < 4; i++) {
                int sg = tid + 256 * i;
                int r = sg >> 3, sc = sg & 7;
                CP_ASYNC16(tb + SWZ(r * 128 + sc * 16),
                           g + (size_t)(m0 + r) * lda + k0 + sc * 8);
            }
        }
        // B tiles: 256 rows -> 8 iters per tile
        #pragma unroll
        for (int t = 0; t < 2; t++) {
            const __nv_bfloat16* g = t ? Bl : Bh;
            const uint32_t tb = stage + 2 * A_TILE_BYTES + t * B_TILE_BYTES;
            #pragma unroll
            for (int i = 0; i < 8; i++) {
                int sg = tid + 256 * i;
                int r = sg >> 3, sc = sg & 7;
                CP_ASYNC16(tb + SWZ(r * 128 + sc * 16),
                           g + (size_t)(n0 + r) * ldb + k0 + sc * 8);
            }
        }
        CP_COMMIT();
    };

    float acc[4][8][4] = {};

    load_chunk(0, 0);
    if (NC > 1) load_chunk(1, 1);

    // lane-derived ldmatrix addressing
    const int lg = lane >> 3, lr = lane & 7;
    const int rowA = warp_m * 64 + lr + (lg & 1) * 8;   // + i*16
    const int kA   = (lg >> 1) * 16;                    // byte offset within k16
    const int rowB = warp_n * 64 + lr + (lg >> 1) * 8;  // + jp*16
    const int kBo  = (lg & 1) * 16;

    for (int c = 0; c < NC; c++) {
        if (c == NC - 1) { CP_WAIT0(); } else { CP_WAIT1(); }
        __syncthreads();

        const uint32_t stage = smb + (c & 1) * STAGE_BYTES;
        const uint32_t aH = stage, aL = stage + A_TILE_BYTES;
        const uint32_t bH = stage + 2 * A_TILE_BYTES, bL = bH + B_TILE_BYTES;

        #pragma unroll
        for (int ks = 0; ks < 4; ks++) {
            const int koA = ks * 32 + kA;
            const int koB = ks * 32 + kBo;
            uint32_t bh[4][4], bl[4][4];
            #pragma unroll
            for (int jp = 0; jp < 4; jp++) {
                uint32_t off = SWZ((rowB + jp * 16) * 128 + koB);
                LDSM4(bh[jp][0], bh[jp][1], bh[jp][2], bh[jp][3], bH + off);
                LDSM4(bl[jp][0], bl[jp][1], bl[jp][2], bl[jp][3], bL + off);
            }
            #pragma unroll
            for (int i = 0; i < 4; i++) {
                uint32_t ah[4], al[4];
                uint32_t off = SWZ((rowA + i * 16) * 128 + koA);
                LDSM4(ah[0], ah[1], ah[2], ah[3], aH + off);
                LDSM4(al[0], al[1], al[2], al[3], aL + off);
                #pragma unroll
                for (int jp = 0; jp < 4; jp++) {
                    MMA16816(acc[i][2 * jp],     ah, bh[jp][0], bh[jp][1]);
                    MMA16816(acc[i][2 * jp + 1], ah, bh[jp][2], bh[jp][3]);
                    MMA16816(acc[i][2 * jp],     al, bh[jp][0], bh[jp][1]);
                    MMA16816(acc[i][2 * jp + 1], al, bh[jp][2], bh[jp][3]);
                    MMA16816(acc[i][2 * jp],     ah, bl[jp][0], bl[jp][1]);
                    MMA16816(acc[i][2 * jp + 1], ah, bl[jp][2], bl[jp][3]);
                }
            }
        }
        __syncthreads();
        if (c + 2 < NC) load_chunk(c + 2, c & 1);
    }

    // --- epilogue: regs -> smem -> global --------------------------------
    float* ep = (float*)smem;            // [128][EPIT]
    const int erow = lane >> 2;
    const int ecol = (lane & 3) * 2;
    #pragma unroll
    for (int i = 0; i < 4; i++) {
        int rb = warp_m * 64 + i * 16 + erow;
        #pragma unroll
        for (int j = 0; j < 8; j++) {
            int cc = warp_n * 64 + j * 8 + ecol;
            ep[rb * EPIT + cc]           = acc[i][j][0];
            ep[rb * EPIT + cc + 1]       = acc[i][j][1];
            ep[(rb + 8) * EPIT + cc]     = acc[i][j][2];
            ep[(rb + 8) * EPIT + cc + 1] = acc[i][j][3];
        }
    }
    __syncthreads();

    if constexpr (MODE == 0 || MODE == 2) {
        float* oF = outF + (size_t)b * sC;
        #pragma unroll
        for (int i = 0; i < 32; i++) {
            int idx = tid + 256 * i;
            int r = idx >> 6, c4 = (idx & 63) * 4;
            float4 o;
            o.x = ep[r * EPIT + c4 + 0];
            o.y = ep[r * EPIT + c4 + 1];
            o.z = ep[r * EPIT + c4 + 2];
            o.w = ep[r * EPIT + c4 + 3];
            if constexpr (MODE == 0) {
                float4 bv = *(const float4*)&bias[n0 + c4];
                o.x += bv.x; o.y += bv.y; o.z += bv.z; o.w += bv.w;
            }
            *(float4*)&oF[(size_t)(m0 + r) * ldc + n0 + c4] = o;
        }
    } else if constexpr (MODE == 1 || MODE == 3) {
        __nv_bfloat16* oH = outH + (size_t)b * sC;
        __nv_bfloat16* oL = outL + (size_t)b * sC;
        #pragma unroll
        for (int i = 0; i < 16; i++) {
            int idx = tid + 256 * i;
            int r = idx >> 5, c8 = (idx & 31) * 8;
            unsigned short hb[8], lb[8];
            #pragma unroll
            for (int j = 0; j < 8; j++) {
                float v = ep[r * EPIT + c8 + j];
                if constexpr (MODE == 1) v = (v + bias[n0 + c8 + j]) * scale;
                __nv_bfloat16 hv = __float2bfloat16(v);
                float lo = v - __bfloat162float(hv);
                __nv_bfloat16 lv = __float2bfloat16(lo);
                hb[j] = *(unsigned short*)&hv;
                lb[j] = *(unsigned short*)&lv;
            }
            size_t off = (size_t)(m0 + r) * ldc + n0 + c8;
            *(uint4*)(oH + off) = *(uint4*)hb;
            *(uint4*)(oL + off) = *(uint4*)lb;
        }
    } else {   // MODE 4: transposed bf16-pair store (V projection -> Vt[b][e][s])
        const int bb = m0 >> 11;          // batch from flat row index
        const int s0 = m0 & (S - 1);
        const float bcol = bias[n0 + tid];
        __nv_bfloat16* oH = outH + ((size_t)bb * E + n0 + tid) * S + s0;
        __nv_bfloat16* oL = outL + ((size_t)bb * E + n0 + tid) * S + s0;
        #pragma unroll
        for (int r0 = 0; r0 < 128; r0 += 8) {
            unsigned short hb[8], lb[8];
            #pragma unroll
            for (int k = 0; k < 8; k++) {
                float v = ep[(r0 + k) * EPIT + tid] + bcol;
                __nv_bfloat16 hv = __float2bfloat16(v);
                float lo = v - __bfloat162float(hv);
                __nv_bfloat16 lv = __float2bfloat16(lo);
                hb[k] = *(unsigned short*)&hv;
                lb[k] = *(unsigned short*)&lv;
            }
            *(uint4*)(oH + r0) = *(uint4*)hb;
            *(uint4*)(oL + r0) = *(uint4*)lb;
        }
    }
}

// ---------------------------------------------------------------------------
// Host launcher
// ---------------------------------------------------------------------------
extern "C" void kernel_launch(void* const* d_in, const int* in_sizes, int n_in,
                              void* d_out, int out_size)
{
    const float* query = (const float*)d_in[0];
    const float* key_  = (const float*)d_in[1];
    const float* value = (const float*)d_in[2];
    const float* Wq = (const float*)d_in[4];
    const float* bq = (const float*)d_in[5];
    const float* Wk = (const float*)d_in[6];
    const float* bk = (const float*)d_in[7];
    const float* Wv = (const float*)d_in[8];
    const float* bv = (const float*)d_in[9];
    const float* Wo = (const float*)d_in[10];
    const float* bo = (const float*)d_in[11];
    float* out = (float*)d_out;

    #define SYM(p, s) void* p; cudaGetSymbolAddress(&p, s)
    SYM(qh, g_qh); SYM(ql, g_ql); SYM(kh, g_kh); SYM(kl, g_kl); SYM(vh, g_vh); SYM(vl, g_vl);
    SYM(wqh, g_wqh); SYM(wql, g_wql); SYM(wkh, g_wkh); SYM(wkl, g_wkl);
    SYM(wvh, g_wvh); SYM(wvl, g_wvl); SYM(woh, g_woh); SYM(wol, g_wol);
    SYM(Qh, g_Qh); SYM(Ql, g_Ql); SYM(Kh, g_Kh); SYM(Kl, g_Kl);
    SYM(Vth, g_Vth); SYM(Vtl, g_Vtl);
    SYM(Sc, g_Sc); SYM(Ph, g_Ph); SYM(Pl, g_Pl); SYM(AOh, g_AOh); SYM(AOl, g_AOl);
    #undef SYM
    typedef __nv_bfloat16 bf;

    cudaFuncSetAttribute((const void*)gemm_mma<0, false, false>, cudaFuncAttributeMaxDynamicSharedMemorySize, SMEM_SZ);
    cudaFuncSetAttribute((const void*)gemm_mma<1, false, false>, cudaFuncAttributeMaxDynamicSharedMemorySize, SMEM_SZ);
    cudaFuncSetAttribute((const void*)gemm_mma<2, true,  false>, cudaFuncAttributeMaxDynamicSharedMemorySize, SMEM_SZ);
    cudaFuncSetAttribute((const void*)gemm_mma<3, false, true >, cudaFuncAttributeMaxDynamicSharedMemorySize, SMEM_SZ);
    cudaFuncSetAttribute((const void*)gemm_mma<4, false, false>, cudaFuncAttributeMaxDynamicSharedMemorySize, SMEM_SZ);

    // 1) fp32 -> bf16 hi/lo conversions
    const int nIn = M_ROWS * E, nW = E * E;
    cvt_pair<<<nIn / 2048, 256>>>(query, (bf*)qh, (bf*)ql, nIn);
    cvt_pair<<<nIn / 2048, 256>>>(key_,  (bf*)kh, (bf*)kl, nIn);
    cvt_pair<<<nIn / 2048, 256>>>(value, (bf*)vh, (bf*)vl, nIn);
    cvt_pair<<<nW / 2048, 256>>>(Wq, (bf*)wqh, (bf*)wql, nW);
    cvt_pair<<<nW / 2048, 256>>>(Wk, (bf*)wkh, (bf*)wkl, nW);
    cvt_pair<<<nW / 2048, 256>>>(Wv, (bf*)wvh, (bf*)wvl, nW);
    cvt_pair<<<nW / 2048, 256>>>(Wo, (bf*)woh, (bf*)wol, nW);

    // 2) projections. Q gets the 1/sqrt(E)=1/32 scale folded in; V writes
    //    its output directly in transposed [b][e][s] bf16-pair layout.
    dim3 gproj(E / TN, M_ROWS / TM, 1);    // (4, 64)
    gemm_mma<1, false, false><<<gproj, 256, SMEM_SZ>>>(
        (bf*)qh, (bf*)ql, (bf*)wqh, (bf*)wql, bq, 0.03125f, nullptr, (bf*)Qh, (bf*)Ql,
        E, E, E, E, 0, 0, 0);
    gemm_mma<1, false, false><<<gproj, 256, SMEM_SZ>>>(
        (bf*)kh, (bf*)kl, (bf*)wkh, (bf*)wkl, bk, 1.0f, nullptr, (bf*)Kh, (bf*)Kl,
        E, E, E, E, 0, 0, 0);
    gemm_mma<4, false, false><<<gproj, 256, SMEM_SZ>>>(
        (bf*)vh, (bf*)vl, (bf*)wvh, (bf*)wvl, bv, 1.0f, nullptr, (bf*)Vth, (bf*)Vtl,
        E, E, E, 0, 0, 0, 0);

    // 3) scores = (Q/32) K^T (causal tiles only), fp32 out
    dim3 gsc(S / TN, S / TM, B);           // (8, 16, 4)
    gemm_mma<2, true, false><<<gsc, 256, SMEM_SZ>>>(
        (bf*)Qh, (bf*)Ql, (bf*)Kh, (bf*)Kl, nullptr, 1.0f, (float*)Sc, nullptr, nullptr,
        E, E, E, S, (size_t)S * E, (size_t)S * E, (size_t)S * S);

    // 4) fused softmax -> bf16-pair P
    softmax_pair<<<B * S, 256>>>((const float*)Sc, (bf*)Ph, (bf*)Pl);

    // 5) attn_out = P @ V  (K clipped at diagonal tile), bf16-pair out
    dim3 gav(E / TN, S / TM, B);           // (4, 16, 4)
    gemm_mma<3, false, true><<<gav, 256, SMEM_SZ>>>(
        (bf*)Ph, (bf*)Pl, (bf*)Vth, (bf*)Vtl, nullptr, 1.0f, nullptr, (bf*)AOh, (bf*)AOl,
        S, S, S, E, (size_t)S * S, (size_t)E * S, (size_t)S * E);

    // 6) output projection -> d_out (fp32 + bias)
    gemm_mma<0, false, false><<<gproj, 256, SMEM_SZ>>>(
        (bf*)AOh, (bf*)AOl, (bf*)woh, (bf*)wol, bo, 1.0f, out, nullptr, nullptr,
        E, E, E, E, 0, 0, 0);
}

// round 6
// speedup vs baseline: 1.5809x; 1.5809x over previous
#include <cuda_runtime.h>
#include <cuda_bf16.h>
#include <cstdint>
#include <math.h>

// ---------------------------------------------------------------------------
// Problem constants
// ---------------------------------------------------------------------------
constexpr int B = 4;
constexpr int S = 2048;
constexpr int E = 1024;
constexpr int M_ROWS = B * S;   // 8192

// GEMM tiling: CTA 128x128, KB=64 bf16 per chunk (128B swizzled rows)
constexpr int TM = 128, TN = 128, KB = 64;
constexpr int TILE_BYTES = 128 * 128;          // 16KB per operand tile
constexpr int STAGE_BYTES = 4 * TILE_BYTES;    // Ah, Al, Bh, Bl = 64KB
constexpr int NSTAGE = 3;
constexpr int SMEM_SZ = NSTAGE * STAGE_BYTES;  // 192KB
constexpr int EPIT = 132;                      // fp32 epilogue pitch (words)

// ---------------------------------------------------------------------------
// Scratch (device globals — no allocations allowed)
// ---------------------------------------------------------------------------
__device__ __nv_bfloat16 g_qh[(size_t)M_ROWS * E], g_ql[(size_t)M_ROWS * E];
__device__ __nv_bfloat16 g_kh[(size_t)M_ROWS * E], g_kl[(size_t)M_ROWS * E];
__device__ __nv_bfloat16 g_vh[(size_t)M_ROWS * E], g_vl[(size_t)M_ROWS * E];
__device__ __nv_bfloat16 g_wqh[(size_t)E * E], g_wql[(size_t)E * E];
__device__ __nv_bfloat16 g_wkh[(size_t)E * E], g_wkl[(size_t)E * E];
__device__ __nv_bfloat16 g_wvh[(size_t)E * E], g_wvl[(size_t)E * E];
__device__ __nv_bfloat16 g_woh[(size_t)E * E], g_wol[(size_t)E * E];
__device__ __nv_bfloat16 g_Qh[(size_t)M_ROWS * E], g_Ql[(size_t)M_ROWS * E];
__device__ __nv_bfloat16 g_Kh[(size_t)M_ROWS * E], g_Kl[(size_t)M_ROWS * E];
__device__ __nv_bfloat16 g_Vth[(size_t)B * E * S], g_Vtl[(size_t)B * E * S];
__device__ float         g_Sc[(size_t)B * S * S];
__device__ __nv_bfloat16 g_Ph[(size_t)B * S * S], g_Pl[(size_t)B * S * S];
__device__ __nv_bfloat16 g_AOh[(size_t)M_ROWS * E], g_AOl[(size_t)M_ROWS * E];

// ---------------------------------------------------------------------------
// PTX helpers (Ampere-compatible only: cp.async, ldmatrix, mma.sync)
// ---------------------------------------------------------------------------
__device__ __forceinline__ uint32_t smem_u32(const void* p) {
    uint32_t a;
    asm("{ .reg .u64 t; cvta.to.shared.u64 t, %1; cvt.u32.u64 %0, t; }" : "=r"(a) : "l"(p));
    return a;
}
#define SWZ(o) ((uint32_t)(o) ^ ((((uint32_t)(o)) >> 3) & 0x70))

#define CP_ASYNC16(dst, src) \
    asm volatile("cp.async.cg.shared.global [%0], [%1], 16;" :: "r"(dst), "l"(src) : "memory")
#define CP_COMMIT() asm volatile("cp.async.commit_group;" ::: "memory")
#define CP_WAIT0()  asm volatile("cp.async.wait_group 0;" ::: "memory")
#define CP_WAIT1()  asm volatile("cp.async.wait_group 1;" ::: "memory")

#define LDSM4(r0, r1, r2, r3, a) \
    asm volatile("ldmatrix.sync.aligned.m8n8.x4.shared.b16 {%0,%1,%2,%3}, [%4];" \
                 : "=r"(r0), "=r"(r1), "=r"(r2), "=r"(r3) : "r"(a))

#define MMA16816(c, a, b0, b1) \
    asm volatile("mma.sync.aligned.m16n8k16.row.col.f32.bf16.bf16.f32 " \
                 "{%0,%1,%2,%3},{%4,%5,%6,%7},{%8,%9},{%0,%1,%2,%3};" \
                 : "+f"((c)[0]), "+f"((c)[1]), "+f"((c)[2]), "+f"((c)[3]) \
                 : "r"((a)[0]), "r"((a)[1]), "r"((a)[2]), "r"((a)[3]), \
                   "r"(b0), "r"(b1))

// ---------------------------------------------------------------------------
// Batched fp32 -> (bf16 hi, bf16 lo) conversions (blockIdx.y selects tensor)
// ---------------------------------------------------------------------------
__device__ __forceinline__ void cvt_body(const float* __restrict__ in,
                                         __nv_bfloat16* __restrict__ h,
                                         __nv_bfloat16* __restrict__ l)
{
    int i = (blockIdx.x * 256 + threadIdx.x) * 8;
    float4 a = *(const float4*)(in + i);
    float4 b2 = *(const float4*)(in + i + 4);
    float v[8] = {a.x, a.y, a.z, a.w, b2.x, b2.y, b2.z, b2.w};
    unsigned short hb[8], lb[8];
    #pragma unroll
    for (int j = 0; j < 8; j++) {
        __nv_bfloat16 hv = __float2bfloat16(v[j]);
        float lo = v[j] - __bfloat162float(hv);
        __nv_bfloat16 lv = __float2bfloat16(lo);
        hb[j] = *(unsigned short*)&hv;
        lb[j] = *(unsigned short*)&lv;
    }
    *(uint4*)(h + i) = *(uint4*)hb;
    *(uint4*)(l + i) = *(uint4*)lb;
}

__global__ __launch_bounds__(256) void cvt3(
    const float* __restrict__ i0, const float* __restrict__ i1, const float* __restrict__ i2,
    __nv_bfloat16* h0, __nv_bfloat16* l0, __nv_bfloat16* h1, __nv_bfloat16* l1,
    __nv_bfloat16* h2, __nv_bfloat16* l2)
{
    const int z = blockIdx.y;
    const float* in = (z == 0) ? i0 : (z == 1) ? i1 : i2;
    __nv_bfloat16* h = (z == 0) ? h0 : (z == 1) ? h1 : h2;
    __nv_bfloat16* l = (z == 0) ? l0 : (z == 1) ? l1 : l2;
    cvt_body(in, h, l);
}

__global__ __launch_bounds__(256) void cvt4(
    const float* __restrict__ i0, const float* __restrict__ i1,
    const float* __restrict__ i2, const float* __restrict__ i3,
    __nv_bfloat16* h0, __nv_bfloat16* l0, __nv_bfloat16* h1, __nv_bfloat16* l1,
    __nv_bfloat16* h2, __nv_bfloat16* l2, __nv_bfloat16* h3, __nv_bfloat16* l3)
{
    const int z = blockIdx.y;
    const float* in = (z == 0) ? i0 : (z == 1) ? i1 : (z == 2) ? i2 : i3;
    __nv_bfloat16* h = (z == 0) ? h0 : (z == 1) ? h1 : (z == 2) ? h2 : h3;
    __nv_bfloat16* l = (z == 0) ? l0 : (z == 1) ? l1 : (z == 2) ? l2 : l3;
    cvt_body(in, h, l);
}

// ---------------------------------------------------------------------------
// Fused causal softmax: fp32 scores -> bf16-pair probabilities (zeros padded
// to the 128-multiple so attn@V can run dense up to the diagonal tile).
// ---------------------------------------------------------------------------
__global__ __launch_bounds__(256) void softmax_pair(const float* __restrict__ Sc,
                                                    __nv_bfloat16* __restrict__ Ph,
                                                    __nv_bfloat16* __restrict__ Pl)
{
    const int row = blockIdx.x;
    const int b = row >> 11, q = row & (S - 1);
    const float* ptr = Sc + (size_t)b * S * S + (size_t)q * S;
    const int len = q + 1;
    const int plen = ((q >> 7) + 1) << 7;
    const int tid = threadIdx.x;

    float vals[8];
    float m = -INFINITY;
    #pragma unroll
    for (int i = 0; i < 8; i++) {
        int k = tid + i * 256;
        vals[i] = (k < len) ? ptr[k] : -INFINITY;
        m = fmaxf(m, vals[i]);
    }
    __shared__ float red[256];
    red[tid] = m;
    __syncthreads();
    for (int s = 128; s > 0; s >>= 1) {
        if (tid < s) red[tid] = fmaxf(red[tid], red[tid + s]);
        __syncthreads();
    }
    m = red[0];
    __syncthreads();
    float sum = 0.f;
    #pragma unroll
    for (int i = 0; i < 8; i++) {
        int k = tid + i * 256;
        vals[i] = (k < len) ? __expf(vals[i] - m) : 0.f;
        sum += vals[i];
    }
    red[tid] = sum;
    __syncthreads();
    for (int s = 128; s > 0; s >>= 1) {
        if (tid < s) red[tid] += red[tid + s];
        __syncthreads();
    }
    const float inv = 1.0f / red[0];

    __nv_bfloat16* ph = Ph + (size_t)b * S * S + (size_t)q * S;
    __nv_bfloat16* pl = Pl + (size_t)b * S * S + (size_t)q * S;
    #pragma unroll
    for (int i = 0; i < 8; i++) {
        int k = tid + i * 256;
        if (k < plen) {
            float p = vals[i] * inv;
            __nv_bfloat16 h = __float2bfloat16(p);
            ph[k] = h;
            pl[k] = __float2bfloat16(p - __bfloat162float(h));
        }
    }
}

// ---------------------------------------------------------------------------
// GEMM core (R3-proven geometry): computes the 128x128 fp32 tile of
// A[M,K]*Bop[N,K]^T (split-bf16, 3 terms) and leaves it in smem ep[128][EPIT].
// 8 warps of 64x32, m16n8k16 via ldmatrix, 3-stage cp.async pipeline.
// ---------------------------------------------------------------------------
__device__ __forceinline__ void gemm_core(
    const __nv_bfloat16* __restrict__ Ah, const __nv_bfloat16* __restrict__ Al,
    const __nv_bfloat16* __restrict__ Bh, const __nv_bfloat16* __restrict__ Bl,
    int m0, int n0, int lda, int ldb, int NC, char* smem)
{
    const uint32_t smb = smem_u32(smem);
    const int tid = threadIdx.x;
    const int wid = tid >> 5, lane = tid & 31;
    const int warp_m = wid >> 2;        // 0..1 -> 64-row half
    const int warp_n = wid & 3;         // 0..3 -> 32-col quarter

    auto load_chunk = [&](int c, int s) {
        const int k0 = c * KB;
        const uint32_t stage = smb + s * STAGE_BYTES;
        const __nv_bfloat16* gp[4] = {Ah, Al, Bh, Bl};
        #pragma unroll
        for (int t = 0; t < 4; t++) {
            const __nv_bfloat16* g = gp[t];
            const int r0 = (t < 2) ? m0 : n0;
            const int ld = (t < 2) ? lda : ldb;
            const uint32_t tbase = stage + t * TILE_BYTES;
            #pragma unroll
            for (int i = 0; i < 4; i++) {
                int sg = tid + 256 * i;
                int r = sg >> 3, sc = sg & 7;
                CP_ASYNC16(tbase + SWZ(r * 128 + sc * 16),
                           g + (size_t)(r0 + r) * ld + k0 + sc * 8);
            }
        }
        CP_COMMIT();
    };

    float acc[4][4][4] = {};

    load_chunk(0, 0);
    if (NC > 1) load_chunk(1, 1);

    const int lg = lane >> 3, lr = lane & 7;
    const int rowA = warp_m * 64 + lr + (lg & 1) * 8;
    const int kA   = (lg >> 1) * 16;
    const int rowB = warp_n * 32 + lr + (lg >> 1) * 8;
    const int kBo  = (lg & 1) * 16;

    for (int c = 0; c < NC; c++) {
        if (c == NC - 1) { CP_WAIT0(); } else { CP_WAIT1(); }
        __syncthreads();
        if (c + 2 < NC) load_chunk(c + 2, (c + 2) % NSTAGE);

        const uint32_t stage = smb + (c % NSTAGE) * STAGE_BYTES;
        const uint32_t aH = stage, aL = stage + TILE_BYTES;
        const uint32_t bH = stage + 2 * TILE_BYTES, bL = stage + 3 * TILE_BYTES;

        #pragma unroll
        for (int ks = 0; ks < 4; ks++) {
            const int koA = ks * 32 + kA;
            const int koB = ks * 32 + kBo;
            uint32_t ah[4][4], al[4][4], bh[2][4], bl[2][4];
            #pragma unroll
            for (int i = 0; i < 4; i++) {
                uint32_t off = SWZ((rowA + i * 16) * 128 + koA);
                LDSM4(ah[i][0], ah[i][1], ah[i][2], ah[i][3], aH + off);
                LDSM4(al[i][0], al[i][1], al[i][2], al[i][3], aL + off);
            }
            #pragma unroll
            for (int p = 0; p < 2; p++) {
                uint32_t off = SWZ((rowB + p * 16) * 128 + koB);
                LDSM4(bh[p][0], bh[p][1], bh[p][2], bh[p][3], bH + off);
                LDSM4(bl[p][0], bl[p][1], bl[p][2], bl[p][3], bL + off);
            }
            #pragma unroll
            for (int i = 0; i < 4; i++) {
                #pragma unroll
                for (int j = 0; j < 4; j++) {
                    const int p = j >> 1, h = (j & 1) * 2;
                    MMA16816(acc[i][j], ah[i], bh[p][h], bh[p][h + 1]);
                    MMA16816(acc[i][j], al[i], bh[p][h], bh[p][h + 1]);
                    MMA16816(acc[i][j], ah[i], bl[p][h], bl[p][h + 1]);
                }
            }
        }
        __syncthreads();
    }

    // regs -> smem ep
    float* ep = (float*)smem;
    const int erow = lane >> 2;
    const int ecol = (lane & 3) * 2;
    #pragma unroll
    for (int i = 0; i < 4; i++) {
        int rbase = warp_m * 64 + i * 16 + erow;
        #pragma unroll
        for (int j = 0; j < 4; j++) {
            int cc = warp_n * 32 + j * 8 + ecol;
            ep[rbase * EPIT + cc]           = acc[i][j][0];
            ep[rbase * EPIT + cc + 1]       = acc[i][j][1];
            ep[(rbase + 8) * EPIT + cc]     = acc[i][j][2];
            ep[(rbase + 8) * EPIT + cc + 1] = acc[i][j][3];
        }
    }
    __syncthreads();
}

// bf16-pair store helper: ep[128][EPIT] (+bias)*scale -> row-major pair arrays
__device__ __forceinline__ void store_pair(
    const float* ep, const float* bias, float scale,
    __nv_bfloat16* oH, __nv_bfloat16* oL, int m0, int n0, int ldc)
{
    const int tid = threadIdx.x;
    #pragma unroll
    for (int i = 0; i < 8; i++) {
        int idx = tid + 256 * i;
        int r = idx >> 4, c8 = (idx & 15) * 8;
        unsigned short hb[8], lb[8];
        #pragma unroll
        for (int j = 0; j < 8; j++) {
            float v = ep[r * EPIT + c8 + j];
            if (bias) v = (v + bias[n0 + c8 + j]) * scale;
            __nv_bfloat16 hv = __float2bfloat16(v);
            float lo = v - __bfloat162float(hv);
            __nv_bfloat16 lv = __float2bfloat16(lo);
            hb[j] = *(unsigned short*)&hv;
            lb[j] = *(unsigned short*)&lv;
        }
        size_t off = (size_t)(m0 + r) * ldc + n0 + c8;
        *(uint4*)(oH + off) = *(uint4*)hb;
        *(uint4*)(oL + off) = *(uint4*)lb;
    }
}

// ---------------------------------------------------------------------------
// Fused Q/K/V projection: blockIdx.z selects tensor. Q folds the 1/32 scale;
// V writes directly in transposed [b][e][s] bf16-pair layout.
// ---------------------------------------------------------------------------
__global__ __launch_bounds__(256, 1) void proj_qkv(
    const __nv_bfloat16* __restrict__ qh, const __nv_bfloat16* __restrict__ ql,
    const __nv_bfloat16* __restrict__ kh, const __nv_bfloat16* __restrict__ kl,
    const __nv_bfloat16* __restrict__ vh, const __nv_bfloat16* __restrict__ vl,
    const __nv_bfloat16* __restrict__ wqh, const __nv_bfloat16* __restrict__ wql,
    const __nv_bfloat16* __restrict__ wkh, const __nv_bfloat16* __restrict__ wkl,
    const __nv_bfloat16* __restrict__ wvh, const __nv_bfloat16* __restrict__ wvl,
    const float* __restrict__ bq, const float* __restrict__ bk, const float* __restrict__ bv,
    __nv_bfloat16* Qh, __nv_bfloat16* Ql, __nv_bfloat16* Kh, __nv_bfloat16* Kl,
    __nv_bfloat16* Vth, __nv_bfloat16* Vtl)
{
    extern __shared__ __align__(1024) char smem[];
    const int z = blockIdx.z;
    const int m0 = blockIdx.y * TM, n0 = blockIdx.x * TN;

    const __nv_bfloat16 *Ah, *Al, *Bh, *Bl;
    const float* bias;
    if (z == 0)      { Ah = qh; Al = ql; Bh = wqh; Bl = wql; bias = bq; }
    else if (z == 1) { Ah = kh; Al = kl; Bh = wkh; Bl = wkl; bias = bk; }
    else             { Ah = vh; Al = vl; Bh = wvh; Bl = wvl; bias = bv; }

    gemm_core(Ah, Al, Bh, Bl, m0, n0, E, E, E / KB, smem);
    const float* ep = (const float*)smem;
    const int tid = threadIdx.x;

    if (z == 0) {
        store_pair(ep, bias, 0.03125f, Qh, Ql, m0, n0, E);
    } else if (z == 1) {
        store_pair(ep, bias, 1.0f, Kh, Kl, m0, n0, E);
    } else {
        // transposed store: V[m0+r][n0+col] -> Vt[b][n0+col][s0+r]
        const int bb = m0 >> 11;
        const int s0 = m0 & (S - 1);
        const int col = tid & 127, half = tid >> 7;   // half selects rows 0-63 / 64-127
        const float bcol = bias[n0 + col];
        __nv_bfloat16* oH = Vth + ((size_t)bb * E + n0 + col) * S + s0 + half * 64;
        __nv_bfloat16* oL = Vtl + ((size_t)bb * E + n0 + col) * S + s0 + half * 64;
        #pragma unroll
        for (int r0 = 0; r0 < 64; r0 += 8) {
            unsigned short hb[8], lb[8];
            #pragma unroll
            for (int k = 0; k < 8; k++) {
                float v = ep[(half * 64 + r0 + k) * EPIT + col] + bcol;
                __nv_bfloat16 hv = __float2bfloat16(v);
                float lo = v - __bfloat162float(hv);
                __nv_bfloat16 lv = __float2bfloat16(lo);
                hb[k] = *(unsigned short*)&hv;
                lb[k] = *(unsigned short*)&lv;
            }
            *(uint4*)(oH + r0) = *(uint4*)hb;
            *(uint4*)(oL + r0) = *(uint4*)lb;
        }
    }
}

// ---------------------------------------------------------------------------
// Scores: Sc[b] tile = (Q/32)[m0:,:] K^T[n0:,:]  (causal tiles only, fp32 out)
// ---------------------------------------------------------------------------
__global__ __launch_bounds__(256, 1) void scores_mma(
    const __nv_bfloat16* __restrict__ Qh, const __nv_bfloat16* __restrict__ Ql,
    const __nv_bfloat16* __restrict__ Kh, const __nv_bfloat16* __restrict__ Kl,
    float* __restrict__ Sc)
{
    extern __shared__ __align__(1024) char smem[];
    const int b = blockIdx.z;
    const int m0 = blockIdx.y * TM, n0 = blockIdx.x * TN;
    if (n0 > m0) return;

    const size_t boff = (size_t)b * S * E;
    gemm_core(Qh + boff, Ql + boff, Kh + boff, Kl + boff, m0, n0, E, E, E / KB, smem);
    const float* ep = (const float*)smem;
    float* oF = Sc + (size_t)b * S * S;
    const int tid = threadIdx.x;
    #pragma unroll
    for (int i = 0; i < 16; i++) {
        int idx = tid + 256 * i;
        int r = idx >> 5, c4 = (idx & 31) * 4;
        float4 o;
        o.x = ep[r * EPIT + c4 + 0];
        o.y = ep[r * EPIT + c4 + 1];
        o.z = ep[r * EPIT + c4 + 2];
        o.w = ep[r * EPIT + c4 + 3];
        *(float4*)&oF[(size_t)(m0 + r) * S + n0 + c4] = o;
    }
}

// ---------------------------------------------------------------------------
// attn_out = P @ V (K clipped at diagonal tile), bf16-pair out
// ---------------------------------------------------------------------------
__global__ __launch_bounds__(256, 1) void attnv_mma(
    const __nv_bfloat16* __restrict__ Ph, const __nv_bfloat16* __restrict__ Pl,
    const __nv_bfloat16* __restrict__ Vth, const __nv_bfloat16* __restrict__ Vtl,
    __nv_bfloat16* AOh, __nv_bfloat16* AOl)
{
    extern __shared__ __align__(1024) char smem[];
    const int b = blockIdx.z;
    const int m0 = blockIdx.y * TM, n0 = blockIdx.x * TN;
    const size_t poff = (size_t)b * S * S, voff = (size_t)b * E * S;

    gemm_core(Ph + poff, Pl + poff, Vth + voff, Vtl + voff,
              m0, n0, S, S, (m0 + TM) / KB, smem);
    const float* ep = (const float*)smem;
    store_pair(ep, nullptr, 1.0f, AOh + (size_t)b * S * E, AOl + (size_t)b * S * E,
               m0, n0, E);
}

// ---------------------------------------------------------------------------
// Output projection: out = AO @ Wo^T + bo (fp32)
// ---------------------------------------------------------------------------
__global__ __launch_bounds__(256, 1) void outproj_mma(
    const __nv_bfloat16* __restrict__ AOh, const __nv_bfloat16* __restrict__ AOl,
    const __nv_bfloat16* __restrict__ woh, const __nv_bfloat16* __restrict__ wol,
    const float* __restrict__ bo, float* __restrict__ out)
{
    extern __shared__ __align__(1024) char smem[];
    const int m0 = blockIdx.y * TM, n0 = blockIdx.x * TN;
    gemm_core(AOh, AOl, woh, wol, m0, n0, E, E, E / KB, smem);
    const float* ep = (const float*)smem;
    const int tid = threadIdx.x;
    #pragma unroll
    for (int i = 0; i < 16; i++) {
        int idx = tid + 256 * i;
        int r = idx >> 5, c4 = (idx & 31) * 4;
        float4 bv = *(const float4*)&bo[n0 + c4];
        float4 o;
        o.x = ep[r * EPIT + c4 + 0] + bv.x;
        o.y = ep[r * EPIT + c4 + 1] + bv.y;
        o.z = ep[r * EPIT + c4 + 2] + bv.z;
        o.w = ep[r * EPIT + c4 + 3] + bv.w;
        *(float4*)&out[(size_t)(m0 + r) * E + n0 + c4] = o;
    }
}

// ---------------------------------------------------------------------------
// Host launcher
// ---------------------------------------------------------------------------
extern "C" void kernel_launch(void* const* d_in, const int* in_sizes, int n_in,
                              void* d_out, int out_size)
{
    const float* query = (const float*)d_in[0];
    const float* key_  = (const float*)d_in[1];
    const float* value = (const float*)d_in[2];
    const float* Wq = (const float*)d_in[4];
    const float* bq = (const float*)d_in[5];
    const float* Wk = (const float*)d_in[6];
    const float* bk = (const float*)d_in[7];
    const float* Wv = (const float*)d_in[8];
    const float* bv = (const float*)d_in[9];
    const float* Wo = (const float*)d_in[10];
    const float* bo = (const float*)d_in[11];
    float* out = (float*)d_out;

    #define SYM(p, s) void* p; cudaGetSymbolAddress(&p, s)
    SYM(qh, g_qh); SYM(ql, g_ql); SYM(kh, g_kh); SYM(kl, g_kl); SYM(vh, g_vh); SYM(vl, g_vl);
    SYM(wqh, g_wqh); SYM(wql, g_wql); SYM(wkh, g_wkh); SYM(wkl, g_wkl);
    SYM(wvh, g_wvh); SYM(wvl, g_wvl); SYM(woh, g_woh); SYM(wol, g_wol);
    SYM(Qh, g_Qh); SYM(Ql, g_Ql); SYM(Kh, g_Kh); SYM(Kl, g_Kl);
    SYM(Vth, g_Vth); SYM(Vtl, g_Vtl);
    SYM(Sc, g_Sc); SYM(Ph, g_Ph); SYM(Pl, g_Pl); SYM(AOh, g_AOh); SYM(AOl, g_AOl);
    #undef SYM
    typedef __nv_bfloat16 bf;

    cudaFuncSetAttribute((const void*)proj_qkv,    cudaFuncAttributeMaxDynamicSharedMemorySize, SMEM_SZ);
    cudaFuncSetAttribute((const void*)scores_mma,  cudaFuncAttributeMaxDynamicSharedMemorySize, SMEM_SZ);
    cudaFuncSetAttribute((const void*)attnv_mma,   cudaFuncAttributeMaxDynamicSharedMemorySize, SMEM_SZ);
    cudaFuncSetAttribute((const void*)outproj_mma, cudaFuncAttributeMaxDynamicSharedMemorySize, SMEM_SZ);

    // 1) fp32 -> bf16 hi/lo conversions (batched)
    const int nIn = M_ROWS * E, nW = E * E;
    cvt3<<<dim3(nIn / 2048, 3), 256>>>(query, key_, value,
        (bf*)qh, (bf*)ql, (bf*)kh, (bf*)kl, (bf*)vh, (bf*)vl);
    cvt4<<<dim3(nW / 2048, 4), 256>>>(Wq, Wk, Wv, Wo,
        (bf*)wqh, (bf*)wql, (bf*)wkh, (bf*)wkl, (bf*)wvh, (bf*)wvl, (bf*)woh, (bf*)wol);

    // 2) fused Q/K/V projections (Q scaled by 1/32, V transposed)
    proj_qkv<<<dim3(E / TN, M_ROWS / TM, 3), 256, SMEM_SZ>>>(
        (bf*)qh, (bf*)ql, (bf*)kh, (bf*)kl, (bf*)vh, (bf*)vl,
        (bf*)wqh, (bf*)wql, (bf*)wkh, (bf*)wkl, (bf*)wvh, (bf*)wvl,
        bq, bk, bv,
        (bf*)Qh, (bf*)Ql, (bf*)Kh, (bf*)Kl, (bf*)Vth, (bf*)Vtl);

    // 3) scores (causal tiles only)
    scores_mma<<<dim3(S / TN, S / TM, B), 256, SMEM_SZ>>>(
        (bf*)Qh, (bf*)Ql, (bf*)Kh, (bf*)Kl, (float*)Sc);

    // 4) fused softmax -> bf16-pair P
    softmax_pair<<<B * S, 256>>>((const float*)Sc, (bf*)Ph, (bf*)Pl);

    // 5) attn_out = P @ V
    attnv_mma<<<dim3(E / TN, S / TM, B), 256, SMEM_SZ>>>(
        (bf*)Ph, (bf*)Pl, (bf*)Vth, (bf*)Vtl, (bf*)AOh, (bf*)AOl);

    // 6) output projection -> d_out
    outproj_mma<<<dim3(E / TN, M_ROWS / TM, 1), 256, SMEM_SZ>>>(
        (bf*)AOh, (bf*)AOl, (bf*)woh, (bf*)wol, bo, out);
}